// round 15
// baseline (speedup 1.0000x reference)
#include <cuda_runtime.h>
#include <math.h>

#define NP 4096
#define NBLK 296
#define NCH 256                          /* 16-element chunks per row */
#define NEG_LOGN (-8.317766166719343f)   /* -log(4096) */
#define LOG2E 1.4426950408889634f
#define LN2   0.6931471805599453f
/* dynamic smem: 4 bias arrays + hmax[4][256] + eps[64] + lists 4*16*256 u8 */
#define QSMEM (((4 * NP) + (4 * NCH) + 64) * 4 + 4 * 16 * NCH)

struct __align__(16) Scratch {
    unsigned short Qxx[(size_t)NP * NP];   // 32 MB quantized
    unsigned short Qyy[(size_t)NP * NP];
    unsigned short QD [(size_t)NP * NP];
    unsigned short QDT[(size_t)NP * NP];
    unsigned sumXX[(size_t)NP * NCH];      // per-chunk (umin | jpos<<16)
    unsigned sumYY[(size_t)NP * NCH];
    unsigned sumD [(size_t)NP * NCH];
    unsigned sumDT[(size_t)NP * NCH];
    float xt[NP * 64], yt[NP * 64];
    float sqx[NP], sqy[NP];
    float pots[8][NP];   // fa0 fa1 gb0 gb1 fba0 fba1 gab0 gab1
    float fin[4][NP];    // f_aa, g_bb, f_ba, g_ab (final)
};
__device__ Scratch S;

__device__ unsigned g_maxsq;

__device__ __forceinline__ float ex2(float x) {
    float y;
    asm("ex2.approx.ftz.f32 %0, %1;" : "=f"(y) : "f"(x));
    return y;
}
__device__ __forceinline__ float lg2(float x) {
    float y;
    asm("lg2.approx.f32 %0, %1;" : "=f"(y) : "f"(x));
    return y;
}

__device__ __forceinline__ float q_scale() {
    float ms = fmaxf(__uint_as_float(g_maxsq), 1e-6f);
    return 2.0f * ms * (1.0f / 65535.0f);
}

// ---------------------------------------------------------------------------
__device__ unsigned g_cnt;
__device__ unsigned g_gen;

__device__ __forceinline__ void gsync() {
    __threadfence();
    __syncthreads();
    if (threadIdx.x == 0) {
        volatile unsigned* vg = &g_gen;
        unsigned my = *vg;
        if (atomicAdd(&g_cnt, 1u) == NBLK - 1u) {
            g_cnt = 0u;
            __threadfence();
            *vg = my + 1u;
        } else {
            while (*vg == my) { }
        }
    }
    __syncthreads();
}

// ---------------------------------------------------------------------------
__global__ void reset_max_kernel() { g_maxsq = 0u; }

__global__ void prep_kernel(const float* __restrict__ x, const float* __restrict__ y,
                            float* __restrict__ xt, float* __restrict__ yt,
                            float* __restrict__ sqx, float* __restrict__ sqy) {
    __shared__ float red[8];
    int p = blockIdx.x * blockDim.x + threadIdx.x;
    float sx = 0.f, sy = 0.f;
    #pragma unroll 8
    for (int c = 0; c < 64; c++) {
        float vx = x[c * NP + p];
        float vy = y[c * NP + p];
        xt[p * 64 + c] = vx;
        yt[p * 64 + c] = vy;
        sx = fmaf(vx, vx, sx);
        sy = fmaf(vy, vy, sy);
    }
    sqx[p] = sx; sqy[p] = sy;
    float mx = fmaxf(sx, sy);
    #pragma unroll
    for (int o = 16; o; o >>= 1)
        mx = fmaxf(mx, __shfl_xor_sync(0xffffffffu, mx, o));
    if ((threadIdx.x & 31) == 0) red[threadIdx.x >> 5] = mx;
    __syncthreads();
    if (threadIdx.x == 0) {
        float m = red[0];
        #pragma unroll
        for (int w = 1; w < 8; w++) m = fmaxf(m, red[w]);
        atomicMax(&g_maxsq, __float_as_uint(m));
    }
}

// ---------------------------------------------------------------------------
// cost + quantize + per-chunk summary (umin | jpos<<16)
// ---------------------------------------------------------------------------
__global__ void cost_quant_kernel(const float* __restrict__ A, const float* __restrict__ Bm,
                                  const float* __restrict__ sqa, const float* __restrict__ sqb,
                                  unsigned short* __restrict__ Q,
                                  unsigned* __restrict__ sum) {
    __shared__ float As[16 * 128];
    __shared__ float Bs[16 * 128];
    int tid = threadIdx.x;
    int tx = tid & 15, ty = tid >> 4;
    int i0 = blockIdx.y * 128, j0 = blockIdx.x * 128;
    float qinv = 1.0f / q_scale();

    float acc[8][8];
    #pragma unroll
    for (int r = 0; r < 8; r++)
        #pragma unroll
        for (int c = 0; c < 8; c++) acc[r][c] = 0.f;

    for (int c0 = 0; c0 < 64; c0 += 16) {
        #pragma unroll
        for (int n = 0; n < 2; n++) {
            int idx = tid + n * 256;
            int r = idx >> 2, q = idx & 3;
            float4 va = *(const float4*)&A[(size_t)(i0 + r) * 64 + c0 + q * 4];
            As[(q * 4 + 0) * 128 + r] = va.x;
            As[(q * 4 + 1) * 128 + r] = va.y;
            As[(q * 4 + 2) * 128 + r] = va.z;
            As[(q * 4 + 3) * 128 + r] = va.w;
            float4 vb = *(const float4*)&Bm[(size_t)(j0 + r) * 64 + c0 + q * 4];
            Bs[(q * 4 + 0) * 128 + r] = vb.x;
            Bs[(q * 4 + 1) * 128 + r] = vb.y;
            Bs[(q * 4 + 2) * 128 + r] = vb.z;
            Bs[(q * 4 + 3) * 128 + r] = vb.w;
        }
        __syncthreads();
        #pragma unroll
        for (int k = 0; k < 16; k++) {
            float a[8], bb[8];
            *(float4*)&a[0]  = *(const float4*)&As[k * 128 + ty * 8];
            *(float4*)&a[4]  = *(const float4*)&As[k * 128 + ty * 8 + 4];
            *(float4*)&bb[0] = *(const float4*)&Bs[k * 128 + tx * 8];
            *(float4*)&bb[4] = *(const float4*)&Bs[k * 128 + tx * 8 + 4];
            #pragma unroll
            for (int r = 0; r < 8; r++)
                #pragma unroll
                for (int c = 0; c < 8; c++)
                    acc[r][c] = fmaf(a[r], bb[c], acc[r][c]);
        }
        __syncthreads();
    }

    float sj[8];
    #pragma unroll
    for (int c = 0; c < 8; c++) sj[c] = sqb[j0 + tx * 8 + c];

    #pragma unroll
    for (int r = 0; r < 8; r++) {
        int i = i0 + ty * 8 + r;
        float si = sqa[i];
        unsigned us[8];
        unsigned lmin = 65535u; int lidx = 0;
        #pragma unroll
        for (int c = 0; c < 8; c++) {
            float o = 0.5f * (si + sj[c] - 2.f * acc[r][c]);
            unsigned u = (unsigned)fminf(fmaxf(rintf(o * qinv), 0.f), 65535.f);
            us[c] = u;
            if (u < lmin) { lmin = u; lidx = c; }
        }
        uint4 w;
        w.x = us[0] | (us[1] << 16);
        w.y = us[2] | (us[3] << 16);
        w.z = us[4] | (us[5] << 16);
        w.w = us[6] | (us[7] << 16);
        *(uint4*)&Q[(size_t)i * NP + j0 + tx * 8] = w;
        // chunk summary: pair lanes (tx even: low 8, tx odd: high 8)
        unsigned omin = __shfl_xor_sync(0xffffffffu, lmin, 1);
        int oidx = __shfl_xor_sync(0xffffffffu, lidx, 1);
        if ((tx & 1) == 0) {
            unsigned jp = (unsigned)lidx;
            unsigned mn = lmin;
            if (omin < mn) { mn = omin; jp = (unsigned)(oidx + 8); }
            sum[(size_t)i * NCH + (j0 >> 4) + (tx >> 1)] = mn | (jp << 16);
        }
    }
}

// ---------------------------------------------------------------------------
// u16 transpose + summary for the transposed matrix
// ---------------------------------------------------------------------------
__global__ void transpose_q_kernel(const unsigned short* __restrict__ A,
                                   unsigned short* __restrict__ B,
                                   unsigned* __restrict__ sumT) {
    __shared__ unsigned short t[32][34];
    int lane = threadIdx.x;
    int x = blockIdx.x * 32 + lane;
    int y = blockIdx.y * 32 + threadIdx.y;
    #pragma unroll
    for (int j = 0; j < 32; j += 8)
        t[threadIdx.y + j][lane] = A[(size_t)(y + j) * NP + x];
    __syncthreads();
    x = blockIdx.y * 32 + lane;
    y = blockIdx.x * 32 + threadIdx.y;
    #pragma unroll
    for (int j = 0; j < 32; j += 8) {
        unsigned v = t[lane][threadIdx.y + j];
        B[(size_t)(y + j) * NP + x] = (unsigned short)v;
        // chunk min within each 16-lane half
        unsigned mn = v; int idx = lane & 15;
        #pragma unroll
        for (int o = 8; o; o >>= 1) {
            unsigned om = __shfl_xor_sync(0xffffffffu, mn, o);
            int oi = __shfl_xor_sync(0xffffffffu, idx, o);
            if (om < mn) { mn = om; idx = oi; }
        }
        if ((lane & 15) == 0) {
            int row = y + j;
            int ch = blockIdx.y * 2 + (lane >> 4);
            sumT[(size_t)row * NCH + ch] = mn | ((unsigned)idx << 16);
        }
    }
}

// ---------------------------------------------------------------------------
__device__ __forceinline__ float u16lo(unsigned w) {
    return __uint_as_float(__byte_perm(w, 0x4B000000u, 0x7410)) - 8388608.0f;
}
__device__ __forceinline__ float u16hi(unsigned w) {
    return __uint_as_float(__byte_perm(w, 0x4B000000u, 0x7432)) - 8388608.0f;
}

// single-ex2 (m,s) merge; m inited to -3e38 sentinel (never NaN)
__device__ __forceinline__ void merge_ms(float& m, float& s, float om, float os) {
    float d = om - m;
    float e1 = ex2(-fabsf(d));
    bool gt = d > 0.f;
    float sn = gt ? fmaf(s, e1, os) : fmaf(os, e1, s);
    if (gt) m = om;
    s = sn;
}

__device__ __forceinline__ void init_eps(float* sh_eps, int tid) {
    if (tid < 56) {
        double e = (tid < 55)
            ? exp(5.545177444479562 - 0.21072103131565253 * (double)tid)
            : 0.0025;
        sh_eps[tid] = (float)e;
    }
}

__device__ __forceinline__ void fill_bias(float* sh, const float* pot,
                                          float inv_e, int tid) {
    const float4* p4 = (const float4*)pot;
    float4* s4 = (float4*)sh;
    #pragma unroll
    for (int q = 0; q < 2; q++) {
        int j = tid + q * 512;
        float4 v = __ldcg(p4 + j);
        float4 o;
        o.x = fmaf(v.x, inv_e, NEG_LOGN) * LOG2E;
        o.y = fmaf(v.y, inv_e, NEG_LOGN) * LOG2E;
        o.z = fmaf(v.z, inv_e, NEG_LOGN) * LOG2E;
        o.w = fmaf(v.w, inv_e, NEG_LOGN) * LOG2E;
        s4[j] = o;
    }
}

// process one stream's row with bound-based chunk skipping
__device__ __forceinline__ float stream_lse(
        const unsigned short* __restrict__ Qrow,
        const unsigned* __restrict__ sumRow,
        const float* __restrict__ h, const float* __restrict__ hmax,
        unsigned char* __restrict__ list, float kq, int lane) {
    // ---- bounds: 8 chunks per lane ----
    float ub[8];
    float Mlb = -3.0e38f;
    #pragma unroll
    for (int k = 0; k < 8; k++) {
        int c = k * 32 + lane;
        unsigned e = sumRow[c];
        float uminf = u16lo(e);
        int jp = (int)(e >> 16);
        float b = fmaf(uminf, kq, 0.f);
        ub[k] = hmax[c] + b;
        float lb = h[c * 16 + jp] + b;
        Mlb = fmaxf(Mlb, lb);
    }
    #pragma unroll
    for (int o = 16; o; o >>= 1)
        Mlb = fmaxf(Mlb, __shfl_xor_sync(0xffffffffu, Mlb, o));
    float thr = Mlb - 25.0f;
    // ---- compact active chunk list ----
    int base = 0;
    #pragma unroll
    for (int k = 0; k < 8; k++) {
        bool f = ub[k] >= thr;
        unsigned msk = __ballot_sync(0xffffffffu, f);
        if (f) {
            int pos = base + __popc(msk & ((1u << lane) - 1u));
            list[pos] = (unsigned char)(k * 32 + lane);
        }
        base += __popc(msk);
    }
    __syncwarp();
    // ---- process active chunks: one chunk per lane ----
    float m = -3.0e38f, s = 0.f;
    for (int i = lane; i < base; i += 32) {
        int c = (int)list[i];
        const uint4* qp = (const uint4*)(Qrow + c * 16);
        uint4 a0 = __ldcg(qp);
        uint4 a1 = __ldcg(qp + 1);
        const float4* hp = (const float4*)(h + c * 16);
        float4 h0 = hp[0], h1 = hp[1], h2 = hp[2], h3 = hp[3];
        float v[16];
        v[0]  = fmaf(u16lo(a0.x), kq, h0.x); v[1]  = fmaf(u16hi(a0.x), kq, h0.y);
        v[2]  = fmaf(u16lo(a0.y), kq, h0.z); v[3]  = fmaf(u16hi(a0.y), kq, h0.w);
        v[4]  = fmaf(u16lo(a0.z), kq, h1.x); v[5]  = fmaf(u16hi(a0.z), kq, h1.y);
        v[6]  = fmaf(u16lo(a0.w), kq, h1.z); v[7]  = fmaf(u16hi(a0.w), kq, h1.w);
        v[8]  = fmaf(u16lo(a1.x), kq, h2.x); v[9]  = fmaf(u16hi(a1.x), kq, h2.y);
        v[10] = fmaf(u16lo(a1.y), kq, h2.z); v[11] = fmaf(u16hi(a1.y), kq, h2.w);
        v[12] = fmaf(u16lo(a1.z), kq, h3.x); v[13] = fmaf(u16hi(a1.z), kq, h3.y);
        v[14] = fmaf(u16lo(a1.w), kq, h3.z); v[15] = fmaf(u16hi(a1.w), kq, h3.w);
        float cm = v[0];
        #pragma unroll
        for (int t = 1; t < 16; t++) cm = fmaxf(cm, v[t]);
        float cs = 0.f;
        #pragma unroll
        for (int t = 0; t < 16; t++) cs += ex2(v[t] - cm);
        merge_ms(m, s, cm, cs);
    }
    // ---- warp reduce (sentinel-safe: merge_ms with both -3e38 keeps s=0) ----
    #pragma unroll
    for (int o = 16; o; o >>= 1) {
        float om = __shfl_xor_sync(0xffffffffu, m, o);
        float os = __shfl_xor_sync(0xffffffffu, s, o);
        merge_ms(m, s, om, os);
    }
    return m + lg2(s);
}

// ---------------------------------------------------------------------------
// quad annealing phase with per-chunk bound skipping.
//   A: Qxx -> f_aa   B: Qyy -> g_bb   C: QD -> f_ba (bias g_ab)
//   D: QDT -> g_ab (bias f_ba).  pots: fa0 fa1 gb0 gb1 fba0 fba1 gab0 gab1
// ---------------------------------------------------------------------------
__global__ void __launch_bounds__(512, 2) quad_phase_kernel(
        const unsigned short* __restrict__ QA, const unsigned short* __restrict__ QB,
        const unsigned short* __restrict__ QC, const unsigned short* __restrict__ QDm,
        const unsigned* __restrict__ sA_, const unsigned* __restrict__ sB_,
        const unsigned* __restrict__ sC_, const unsigned* __restrict__ sD_,
        float* __restrict__ pots, float* __restrict__ fin) {
    extern __shared__ __align__(16) float sm[];
    float* shH   = sm;                    // 4 * NP
    float* hmaxs = sm + 4 * NP;           // 4 * NCH
    float* sh_eps = hmaxs + 4 * NCH;      // 64
    unsigned char* lists = (unsigned char*)(sh_eps + 64);  // 4*16*NCH

    int tid = threadIdx.x, lane = tid & 31, warp = tid >> 5;
    int row = warp * NBLK + (int)blockIdx.x;
    bool active = row < NP;
    int prow = active ? row : 0;
    init_eps(sh_eps, tid);
    float qs = q_scale();
    const unsigned short* Qr[4] = {
        QA + (size_t)prow * NP, QB + (size_t)prow * NP,
        QC + (size_t)prow * NP, QDm + (size_t)prow * NP };
    const unsigned* Sr[4] = {
        sA_ + (size_t)prow * NCH, sB_ + (size_t)prow * NCH,
        sC_ + (size_t)prow * NCH, sD_ + (size_t)prow * NCH };
    int cur = 0;
    __syncthreads();

    for (int t = 0; t <= 57; t++) {
        int ke = (t == 0) ? 0 : (t == 57 ? 55 : t - 1);
        float e = sh_eps[ke];
        float inv_e = 1.f / e;
        float kq = -qs * inv_e * LOG2E;

        if (t == 0) {
            for (int j = tid; j < 4 * NP; j += 512)
                shH[j] = NEG_LOGN * LOG2E;
        } else {
            fill_bias(shH + 0 * NP, pots + (0 + cur) * NP, inv_e, tid);  // fa
            fill_bias(shH + 1 * NP, pots + (2 + cur) * NP, inv_e, tid);  // gb
            fill_bias(shH + 2 * NP, pots + (6 + cur) * NP, inv_e, tid);  // gab->f_ba
            fill_bias(shH + 3 * NP, pots + (4 + cur) * NP, inv_e, tid);  // fba->g_ab
        }
        __syncthreads();
        // per-chunk h max (1024 chunk-maxes over 512 threads)
        #pragma unroll
        for (int q = 0; q < 2; q++) {
            int idx = tid + q * 512;
            const float4* hp = (const float4*)(shH + idx * 16);
            float4 a = hp[0], b = hp[1], c = hp[2], d = hp[3];
            float mx = fmaxf(fmaxf(fmaxf(a.x, a.y), fmaxf(a.z, a.w)),
                             fmaxf(fmaxf(b.x, b.y), fmaxf(b.z, b.w)));
            mx = fmaxf(mx, fmaxf(fmaxf(c.x, c.y), fmaxf(c.z, c.w)));
            mx = fmaxf(mx, fmaxf(fmaxf(d.x, d.y), fmaxf(d.z, d.w)));
            hmaxs[idx] = mx;
        }
        __syncthreads();

        float ls[4];
        #pragma unroll
        for (int s4 = 0; s4 < 4; s4++) {
            ls[s4] = stream_lse(Qr[s4], Sr[s4], shH + s4 * NP,
                                hmaxs + s4 * NCH,
                                lists + (s4 * 16 + warp) * NCH, kq, lane);
        }

        if (lane == 0 && active) {
            float nel = -e * LN2;
            float vA = nel * ls[0];
            float vB = nel * ls[1];
            float vC = nel * ls[2];
            float vD = nel * ls[3];
            if (t == 57) {
                fin[0 * NP + row] = vA;
                fin[1 * NP + row] = vB;
                fin[2 * NP + row] = vC;
                fin[3 * NP + row] = vD;
            } else if (t == 0) {
                __stcg(&pots[(0 + 1) * NP + row], vA);
                __stcg(&pots[(2 + 1) * NP + row], vB);
                __stcg(&pots[(4 + 1) * NP + row], vC);
                __stcg(&pots[(6 + 1) * NP + row], vD);
            } else {
                int nx = cur ^ 1;
                __stcg(&pots[(0 + nx) * NP + row],
                       0.5f * __ldcg(&pots[(0 + cur) * NP + row]) + 0.5f * vA);
                __stcg(&pots[(2 + nx) * NP + row],
                       0.5f * __ldcg(&pots[(2 + cur) * NP + row]) + 0.5f * vB);
                __stcg(&pots[(4 + nx) * NP + row],
                       0.5f * __ldcg(&pots[(4 + cur) * NP + row]) + 0.5f * vC);
                __stcg(&pots[(6 + nx) * NP + row],
                       0.5f * __ldcg(&pots[(6 + cur) * NP + row]) + 0.5f * vD);
            }
        }
        if (t == 0) cur = 1; else if (t < 57) cur ^= 1;
        if (t < 57) gsync();
    }
}

// ---------------------------------------------------------------------------
__global__ void loss_reduce(const float* __restrict__ fin, float* __restrict__ out, int first) {
    __shared__ float red[256];
    int tid = threadIdx.x;
    float a = 0.f;
    for (int j = tid; j < NP; j += 256)
        a += (fin[2 * NP + j] - fin[0 * NP + j]) + (fin[3 * NP + j] - fin[1 * NP + j]);
    red[tid] = a;
    __syncthreads();
    for (int sft = 128; sft; sft >>= 1) {
        if (tid < sft) red[tid] += red[tid + sft];
        __syncthreads();
    }
    if (tid == 0) {
        float v = red[0] * (1.0f / NP) * 0.25f;
        if (first) *out = v; else *out += v;
    }
}

// ---------------------------------------------------------------------------
extern "C" void kernel_launch(void* const* d_in, const int* in_sizes, int n_in,
                              void* d_out, int out_size) {
    (void)in_sizes; (void)n_in; (void)out_size;
    const float* x = (const float*)d_in[0];
    const float* y = (const float*)d_in[1];
    float* out = (float*)d_out;

    Scratch* sp = nullptr;
    cudaGetSymbolAddress((void**)&sp, S);
    float* xt  = sp->xt;  float* yt  = sp->yt;
    float* sqx = sp->sqx; float* sqy = sp->sqy;
    float* pots = (float*)sp->pots;
    float* fin  = (float*)sp->fin;

    cudaFuncSetAttribute(quad_phase_kernel,
                         cudaFuncAttributeMaxDynamicSharedMemorySize, QSMEM);
    cudaFuncSetAttribute(quad_phase_kernel,
                         cudaFuncAttributePreferredSharedMemoryCarveout, 100);

    for (int b = 0; b < 4; b++) {
        const float* xb = x + (size_t)b * 64 * NP;
        const float* yb = y + (size_t)b * 64 * NP;

        reset_max_kernel<<<1, 1>>>();
        prep_kernel<<<16, 256>>>(xb, yb, xt, yt, sqx, sqy);
        cost_quant_kernel<<<dim3(32, 32), 256>>>(xt, xt, sqx, sqx, sp->Qxx, sp->sumXX);
        cost_quant_kernel<<<dim3(32, 32), 256>>>(yt, yt, sqy, sqy, sp->Qyy, sp->sumYY);
        cost_quant_kernel<<<dim3(32, 32), 256>>>(xt, yt, sqx, sqy, sp->QD,  sp->sumD);
        transpose_q_kernel<<<dim3(128, 128), dim3(32, 8)>>>(sp->QD, sp->QDT, sp->sumDT);

        quad_phase_kernel<<<NBLK, 512, QSMEM>>>(sp->Qxx, sp->Qyy, sp->QD, sp->QDT,
                                                sp->sumXX, sp->sumYY, sp->sumD,
                                                sp->sumDT, pots, fin);

        loss_reduce<<<1, 256>>>(fin, out, b == 0 ? 1 : 0);
    }
}

// round 17
// speedup vs baseline: 1.2829x; 1.2829x over previous
#include <cuda_runtime.h>
#include <math.h>

#define NP 4096
#define NBLK 296
#define NEG_LOGN (-8.317766166719343f)   /* -log(4096) */
#define LOG2E 1.4426950408889634f
#define LN2   0.6931471805599453f
/* dynamic smem: 4 bias arrays + eps[64] + hseg[32] */
#define QSMEM ((4 * NP + 64 + 32) * 4)

struct __align__(16) Scratch {
    unsigned short Qxx[(size_t)NP * NP];   // 32 MB quantized
    unsigned short Qyy[(size_t)NP * NP];
    unsigned short QD [(size_t)NP * NP];
    unsigned short QDT[(size_t)NP * NP];
    unsigned segmin[4][NP * 8];            // per-row per-512col-segment min u
    unsigned rowmin[4][NP];                // per-row (u<<16 | jmin)
    float xt[NP * 64], yt[NP * 64];
    float sqx[NP], sqy[NP];
    float pots[8][NP];   // fa0 fa1 gb0 gb1 fba0 fba1 gab0 gab1
    float fin[4][NP];    // f_aa, g_bb, f_ba, g_ab (final)
};
__device__ Scratch S;

__device__ unsigned g_maxsq;

__device__ __forceinline__ float ex2(float x) {
    float y;
    asm("ex2.approx.ftz.f32 %0, %1;" : "=f"(y) : "f"(x));
    return y;
}
__device__ __forceinline__ float lg2(float x) {
    float y;
    asm("lg2.approx.f32 %0, %1;" : "=f"(y) : "f"(x));
    return y;
}

__device__ __forceinline__ float q_scale() {
    float ms = fmaxf(__uint_as_float(g_maxsq), 1e-6f);
    return 2.0f * ms * (1.0f / 65535.0f);
}

// ---------------------------------------------------------------------------
__device__ unsigned g_cnt;
__device__ unsigned g_gen;

__device__ __forceinline__ void gsync() {
    __threadfence();
    __syncthreads();
    if (threadIdx.x == 0) {
        volatile unsigned* vg = &g_gen;
        unsigned my = *vg;
        if (atomicAdd(&g_cnt, 1u) == NBLK - 1u) {
            g_cnt = 0u;
            __threadfence();
            *vg = my + 1u;
        } else {
            while (*vg == my) { }
        }
    }
    __syncthreads();
}

// ---------------------------------------------------------------------------
__global__ void reset_max_kernel() { g_maxsq = 0u; }

__global__ void init_min_kernel(unsigned* __restrict__ p, int n) {
    int i = blockIdx.x * 256 + threadIdx.x;
    if (i < n) p[i] = 0xFFFFFFFFu;
}

__global__ void prep_kernel(const float* __restrict__ x, const float* __restrict__ y,
                            float* __restrict__ xt, float* __restrict__ yt,
                            float* __restrict__ sqx, float* __restrict__ sqy) {
    __shared__ float red[8];
    int p = blockIdx.x * blockDim.x + threadIdx.x;
    float sx = 0.f, sy = 0.f;
    #pragma unroll 8
    for (int c = 0; c < 64; c++) {
        float vx = x[c * NP + p];
        float vy = y[c * NP + p];
        xt[p * 64 + c] = vx;
        yt[p * 64 + c] = vy;
        sx = fmaf(vx, vx, sx);
        sy = fmaf(vy, vy, sy);
    }
    sqx[p] = sx; sqy[p] = sy;
    float mx = fmaxf(sx, sy);
    #pragma unroll
    for (int o = 16; o; o >>= 1)
        mx = fmaxf(mx, __shfl_xor_sync(0xffffffffu, mx, o));
    if ((threadIdx.x & 31) == 0) red[threadIdx.x >> 5] = mx;
    __syncthreads();
    if (threadIdx.x == 0) {
        float m = red[0];
        #pragma unroll
        for (int w = 1; w < 8; w++) m = fmaxf(m, red[w]);
        atomicMax(&g_maxsq, __float_as_uint(m));
    }
}

// ---------------------------------------------------------------------------
// cost + quantize + (per-row tile min -> segmin/rowmin atomics)
// ---------------------------------------------------------------------------
__global__ void cost_quant_kernel(const float* __restrict__ A, const float* __restrict__ Bm,
                                  const float* __restrict__ sqa, const float* __restrict__ sqb,
                                  unsigned short* __restrict__ Q,
                                  unsigned* __restrict__ segmin,
                                  unsigned* __restrict__ rowmin) {
    __shared__ float As[16 * 128];
    __shared__ float Bs[16 * 128];
    int tid = threadIdx.x;
    int tx = tid & 15, ty = tid >> 4;
    int i0 = blockIdx.y * 128, j0 = blockIdx.x * 128;
    float qinv = 1.0f / q_scale();

    float acc[8][8];
    #pragma unroll
    for (int r = 0; r < 8; r++)
        #pragma unroll
        for (int c = 0; c < 8; c++) acc[r][c] = 0.f;

    for (int c0 = 0; c0 < 64; c0 += 16) {
        #pragma unroll
        for (int n = 0; n < 2; n++) {
            int idx = tid + n * 256;
            int r = idx >> 2, q = idx & 3;
            float4 va = *(const float4*)&A[(size_t)(i0 + r) * 64 + c0 + q * 4];
            As[(q * 4 + 0) * 128 + r] = va.x;
            As[(q * 4 + 1) * 128 + r] = va.y;
            As[(q * 4 + 2) * 128 + r] = va.z;
            As[(q * 4 + 3) * 128 + r] = va.w;
            float4 vb = *(const float4*)&Bm[(size_t)(j0 + r) * 64 + c0 + q * 4];
            Bs[(q * 4 + 0) * 128 + r] = vb.x;
            Bs[(q * 4 + 1) * 128 + r] = vb.y;
            Bs[(q * 4 + 2) * 128 + r] = vb.z;
            Bs[(q * 4 + 3) * 128 + r] = vb.w;
        }
        __syncthreads();
        #pragma unroll
        for (int k = 0; k < 16; k++) {
            float a[8], bb[8];
            *(float4*)&a[0]  = *(const float4*)&As[k * 128 + ty * 8];
            *(float4*)&a[4]  = *(const float4*)&As[k * 128 + ty * 8 + 4];
            *(float4*)&bb[0] = *(const float4*)&Bs[k * 128 + tx * 8];
            *(float4*)&bb[4] = *(const float4*)&Bs[k * 128 + tx * 8 + 4];
            #pragma unroll
            for (int r = 0; r < 8; r++)
                #pragma unroll
                for (int c = 0; c < 8; c++)
                    acc[r][c] = fmaf(a[r], bb[c], acc[r][c]);
        }
        __syncthreads();
    }

    float sj[8];
    #pragma unroll
    for (int c = 0; c < 8; c++) sj[c] = sqb[j0 + tx * 8 + c];

    int seg = j0 >> 9;
    #pragma unroll
    for (int r = 0; r < 8; r++) {
        int i = i0 + ty * 8 + r;
        float si = sqa[i];
        unsigned us[8];
        unsigned pmin = 0xFFFFFFFFu;
        #pragma unroll
        for (int c = 0; c < 8; c++) {
            float o = 0.5f * (si + sj[c] - 2.f * acc[r][c]);
            unsigned u = (unsigned)fminf(fmaxf(rintf(o * qinv), 0.f), 65535.f);
            us[c] = u;
            unsigned p = (u << 16) | (unsigned)(j0 + tx * 8 + c);
            pmin = min(pmin, p);
        }
        uint4 w;
        w.x = us[0] | (us[1] << 16);
        w.y = us[2] | (us[3] << 16);
        w.z = us[4] | (us[5] << 16);
        w.w = us[6] | (us[7] << 16);
        *(uint4*)&Q[(size_t)i * NP + j0 + tx * 8] = w;
        // reduce packed min over the 16 tx lanes
        #pragma unroll
        for (int o = 8; o; o >>= 1)
            pmin = min(pmin, __shfl_xor_sync(0xffffffffu, pmin, o, 16));
        if (tx == 0) {
            atomicMin(&rowmin[i], pmin);
            atomicMin(&segmin[(size_t)i * 8 + seg], pmin >> 16);
        }
    }
}

// ---------------------------------------------------------------------------
// u16 transpose + segmin/rowmin for the transposed matrix
// ---------------------------------------------------------------------------
__global__ void transpose_q_kernel(const unsigned short* __restrict__ A,
                                   unsigned short* __restrict__ B,
                                   unsigned* __restrict__ segminT,
                                   unsigned* __restrict__ rowminT) {
    __shared__ unsigned short t[32][34];
    int lane = threadIdx.x;
    int x = blockIdx.x * 32 + lane;
    int y = blockIdx.y * 32 + threadIdx.y;
    #pragma unroll
    for (int j = 0; j < 32; j += 8)
        t[threadIdx.y + j][lane] = A[(size_t)(y + j) * NP + x];
    __syncthreads();
    x = blockIdx.y * 32 + lane;
    y = blockIdx.x * 32 + threadIdx.y;
    int seg = (blockIdx.y * 32) >> 9;
    #pragma unroll
    for (int j = 0; j < 32; j += 8) {
        unsigned v = t[lane][threadIdx.y + j];
        B[(size_t)(y + j) * NP + x] = (unsigned short)v;
        unsigned p = (v << 16) | (unsigned)x;
        #pragma unroll
        for (int o = 16; o; o >>= 1)
            p = min(p, __shfl_xor_sync(0xffffffffu, p, o));
        if (lane == 0) {
            int row = y + j;
            atomicMin(&rowminT[row], p);
            atomicMin(&segminT[(size_t)row * 8 + seg], p >> 16);
        }
    }
}

// ---------------------------------------------------------------------------
__device__ __forceinline__ float u16lo(unsigned w) {
    return __uint_as_float(__byte_perm(w, 0x4B000000u, 0x7410)) - 8388608.0f;
}
__device__ __forceinline__ float u16hi(unsigned w) {
    return __uint_as_float(__byte_perm(w, 0x4B000000u, 0x7432)) - 8388608.0f;
}

// single-ex2 (m,s) merge
__device__ __forceinline__ void merge_ms(float& m, float& s, float om, float os) {
    float d = om - m;
    float e1 = ex2(-fabsf(d));
    bool gt = d > 0.f;
    float sn = gt ? fmaf(s, e1, os) : fmaf(os, e1, s);
    if (gt) m = om;
    s = sn;
}

// one 16-element chunk of the online LSE with running-max skip
__device__ __forceinline__ void chunk16q(uint4 a0, uint4 a1,
                                         const float4* __restrict__ h,
                                         float kq, float& m, float& s) {
    float4 h0 = h[0], h1 = h[1], h2 = h[64], h3 = h[65];
    float v[16];
    v[0]  = fmaf(u16lo(a0.x), kq, h0.x); v[1]  = fmaf(u16hi(a0.x), kq, h0.y);
    v[2]  = fmaf(u16lo(a0.y), kq, h0.z); v[3]  = fmaf(u16hi(a0.y), kq, h0.w);
    v[4]  = fmaf(u16lo(a0.z), kq, h1.x); v[5]  = fmaf(u16hi(a0.z), kq, h1.y);
    v[6]  = fmaf(u16lo(a0.w), kq, h1.z); v[7]  = fmaf(u16hi(a0.w), kq, h1.w);
    v[8]  = fmaf(u16lo(a1.x), kq, h2.x); v[9]  = fmaf(u16hi(a1.x), kq, h2.y);
    v[10] = fmaf(u16lo(a1.y), kq, h2.z); v[11] = fmaf(u16hi(a1.y), kq, h2.w);
    v[12] = fmaf(u16lo(a1.z), kq, h3.x); v[13] = fmaf(u16hi(a1.z), kq, h3.y);
    v[14] = fmaf(u16lo(a1.w), kq, h3.z); v[15] = fmaf(u16hi(a1.w), kq, h3.w);
    float cm = v[0];
    #pragma unroll
    for (int t = 1; t < 16; t++) cm = fmaxf(cm, v[t]);
    if (__all_sync(0xffffffffu, cm < m - 25.0f)) return;
    float cs = 0.f;
    #pragma unroll
    for (int t = 0; t < 16; t++) cs += ex2(v[t] - cm);
    merge_ms(m, s, cm, cs);
}

// one stream's row LSE with seg-level load skip + exact row seed.
// hseg8: per-seg max of h (smem, block-uniform). sv: lane's segmin (lane&7).
__device__ __forceinline__ float stream_lse(
        const uint4* __restrict__ Q4, const float* __restrict__ h,
        const float* __restrict__ hseg8, unsigned sv, unsigned rowm,
        float kq, int lane) {
    float lb = h[rowm & 0xFFFFu] + kq * (float)(rowm >> 16);
    float thr = lb - 25.0f;
    float m = lb, s = 0.f;
    const float4* H = (const float4*)h;
    #pragma unroll
    for (int seg = 0; seg < 8; seg++) {
        unsigned smv = __shfl_sync(0xffffffffu, sv, seg);
        // ub over the 512-element segment; warp-uniform skip (loads + exps)
        if (hseg8[seg] + kq * (float)smv < thr) continue;
        int sa = seg * 64 + lane;
        uint4 x0 = __ldcg(Q4 + sa);
        uint4 x1 = __ldcg(Q4 + sa + 32);
        chunk16q(x0, x1, H + sa * 2, kq, m, s);
    }
    #pragma unroll
    for (int o = 16; o; o >>= 1) {
        float om = __shfl_xor_sync(0xffffffffu, m, o);
        float os = __shfl_xor_sync(0xffffffffu, s, o);
        merge_ms(m, s, om, os);
    }
    return m + lg2(s);
}

__device__ __forceinline__ void init_eps(float* sh_eps, int tid) {
    if (tid < 56) {
        double e = (tid < 55)
            ? exp(5.545177444479562 - 0.21072103131565253 * (double)tid)
            : 0.0025;
        sh_eps[tid] = (float)e;
    }
}

__device__ __forceinline__ void fill_bias(float* sh, const float* pot,
                                          float inv_e, int tid) {
    const float4* p4 = (const float4*)pot;
    float4* s4 = (float4*)sh;
    #pragma unroll
    for (int q = 0; q < 2; q++) {
        int j = tid + q * 512;
        float4 v = __ldcg(p4 + j);
        float4 o;
        o.x = fmaf(v.x, inv_e, NEG_LOGN) * LOG2E;
        o.y = fmaf(v.y, inv_e, NEG_LOGN) * LOG2E;
        o.z = fmaf(v.z, inv_e, NEG_LOGN) * LOG2E;
        o.w = fmaf(v.w, inv_e, NEG_LOGN) * LOG2E;
        s4[j] = o;
    }
}

// ---------------------------------------------------------------------------
// quad annealing phase (R14 structure + segment load-skip + row seed)
//   A: Qxx -> f_aa   B: Qyy -> g_bb   C: QD -> f_ba (bias g_ab)
//   D: QDT -> g_ab (bias f_ba).  pots: fa0 fa1 gb0 gb1 fba0 fba1 gab0 gab1
// ---------------------------------------------------------------------------
__global__ void __launch_bounds__(512, 2) quad_phase_kernel(
        const unsigned short* __restrict__ QA, const unsigned short* __restrict__ QB,
        const unsigned short* __restrict__ QC, const unsigned short* __restrict__ QDm,
        const unsigned* __restrict__ segminB, const unsigned* __restrict__ rowminB,
        float* __restrict__ pots, float* __restrict__ fin) {
    extern __shared__ __align__(16) float sm[];
    float* shH = sm;                  // 4 * NP
    float* sh_eps = sm + 4 * NP;      // 64
    float* hsegs = sh_eps + 64;       // 32: [stream*8 + seg]

    int tid = threadIdx.x, lane = tid & 31, warp = tid >> 5;   // 16 warps
    int row = warp * NBLK + (int)blockIdx.x;
    bool active = row < NP;
    int prow = active ? row : 0;
    init_eps(sh_eps, tid);
    float qs = q_scale();
    const uint4* Q4[4] = {
        (const uint4*)(QA  + (size_t)prow * NP),
        (const uint4*)(QB  + (size_t)prow * NP),
        (const uint4*)(QC  + (size_t)prow * NP),
        (const uint4*)(QDm + (size_t)prow * NP) };
    // per-lane segmin (lane&7), per-stream rowmin
    unsigned sv[4], rm[4];
    #pragma unroll
    for (int s4 = 0; s4 < 4; s4++) {
        sv[s4] = segminB[(size_t)s4 * NP * 8 + (size_t)prow * 8 + (lane & 7)];
        rm[s4] = rowminB[(size_t)s4 * NP + prow];
    }
    int cur = 0;
    __syncthreads();

    for (int t = 0; t <= 57; t++) {
        int ke = (t == 0) ? 0 : (t == 57 ? 55 : t - 1);
        float e = sh_eps[ke];
        float inv_e = 1.f / e;
        float kq = -qs * inv_e * LOG2E;

        if (t == 0) {
            for (int j = tid; j < 4 * NP; j += 512)
                shH[j] = NEG_LOGN * LOG2E;
        } else {
            fill_bias(shH + 0 * NP, pots + (0 + cur) * NP, inv_e, tid);  // fa
            fill_bias(shH + 1 * NP, pots + (2 + cur) * NP, inv_e, tid);  // gb
            fill_bias(shH + 2 * NP, pots + (6 + cur) * NP, inv_e, tid);  // gab->f_ba
            fill_bias(shH + 3 * NP, pots + (4 + cur) * NP, inv_e, tid);  // fba->g_ab
        }
        __syncthreads();
        // hseg: 32 (stream,seg) entries over 16 warps -> 2 per warp
        #pragma unroll
        for (int q = 0; q < 2; q++) {
            int w = warp + q * 16;     // 0..31: stream w>>3, seg w&7
            const float4* hp = (const float4*)(shH + (w >> 3) * NP + (w & 7) * 512);
            float mx = -3.0e38f;
            #pragma unroll
            for (int k = 0; k < 4; k++) {
                float4 v = hp[lane * 4 + k];
                mx = fmaxf(mx, fmaxf(fmaxf(v.x, v.y), fmaxf(v.z, v.w)));
            }
            #pragma unroll
            for (int o = 16; o; o >>= 1)
                mx = fmaxf(mx, __shfl_xor_sync(0xffffffffu, mx, o));
            if (lane == 0) hsegs[w] = mx;
        }
        __syncthreads();

        float ls[4];
        #pragma unroll
        for (int s4 = 0; s4 < 4; s4++)
            ls[s4] = stream_lse(Q4[s4], shH + s4 * NP, hsegs + s4 * 8,
                                sv[s4], rm[s4], kq, lane);

        if (lane == 0 && active) {
            float nel = -e * LN2;
            float vA = nel * ls[0];
            float vB = nel * ls[1];
            float vC = nel * ls[2];
            float vD = nel * ls[3];
            if (t == 57) {
                fin[0 * NP + row] = vA;
                fin[1 * NP + row] = vB;
                fin[2 * NP + row] = vC;
                fin[3 * NP + row] = vD;
            } else if (t == 0) {
                __stcg(&pots[(0 + 1) * NP + row], vA);
                __stcg(&pots[(2 + 1) * NP + row], vB);
                __stcg(&pots[(4 + 1) * NP + row], vC);
                __stcg(&pots[(6 + 1) * NP + row], vD);
            } else {
                int nx = cur ^ 1;
                __stcg(&pots[(0 + nx) * NP + row],
                       0.5f * __ldcg(&pots[(0 + cur) * NP + row]) + 0.5f * vA);
                __stcg(&pots[(2 + nx) * NP + row],
                       0.5f * __ldcg(&pots[(2 + cur) * NP + row]) + 0.5f * vB);
                __stcg(&pots[(4 + nx) * NP + row],
                       0.5f * __ldcg(&pots[(4 + cur) * NP + row]) + 0.5f * vC);
                __stcg(&pots[(6 + nx) * NP + row],
                       0.5f * __ldcg(&pots[(6 + cur) * NP + row]) + 0.5f * vD);
            }
        }
        if (t == 0) cur = 1; else if (t < 57) cur ^= 1;
        if (t < 57) gsync();
    }
}

// ---------------------------------------------------------------------------
__global__ void loss_reduce(const float* __restrict__ fin, float* __restrict__ out, int first) {
    __shared__ float red[256];
    int tid = threadIdx.x;
    float a = 0.f;
    for (int j = tid; j < NP; j += 256)
        a += (fin[2 * NP + j] - fin[0 * NP + j]) + (fin[3 * NP + j] - fin[1 * NP + j]);
    red[tid] = a;
    __syncthreads();
    for (int sft = 128; sft; sft >>= 1) {
        if (tid < sft) red[tid] += red[tid + sft];
        __syncthreads();
    }
    if (tid == 0) {
        float v = red[0] * (1.0f / NP) * 0.25f;
        if (first) *out = v; else *out += v;
    }
}

// ---------------------------------------------------------------------------
extern "C" void kernel_launch(void* const* d_in, const int* in_sizes, int n_in,
                              void* d_out, int out_size) {
    (void)in_sizes; (void)n_in; (void)out_size;
    const float* x = (const float*)d_in[0];
    const float* y = (const float*)d_in[1];
    float* out = (float*)d_out;

    Scratch* sp = nullptr;
    cudaGetSymbolAddress((void**)&sp, S);
    float* xt  = sp->xt;  float* yt  = sp->yt;
    float* sqx = sp->sqx; float* sqy = sp->sqy;
    float* pots = (float*)sp->pots;
    float* fin  = (float*)sp->fin;
    unsigned* segB = &sp->segmin[0][0];
    unsigned* rowB = &sp->rowmin[0][0];
    const int nmin = 4 * NP * 8 + 4 * NP;   // segmin + rowmin contiguous

    cudaFuncSetAttribute(quad_phase_kernel,
                         cudaFuncAttributeMaxDynamicSharedMemorySize, QSMEM);
    cudaFuncSetAttribute(quad_phase_kernel,
                         cudaFuncAttributePreferredSharedMemoryCarveout, 100);

    for (int b = 0; b < 4; b++) {
        const float* xb = x + (size_t)b * 64 * NP;
        const float* yb = y + (size_t)b * 64 * NP;

        reset_max_kernel<<<1, 1>>>();
        init_min_kernel<<<(nmin + 255) / 256, 256>>>(segB, nmin);
        prep_kernel<<<16, 256>>>(xb, yb, xt, yt, sqx, sqy);
        cost_quant_kernel<<<dim3(32, 32), 256>>>(xt, xt, sqx, sqx, sp->Qxx,
                                                 &sp->segmin[0][0], &sp->rowmin[0][0]);
        cost_quant_kernel<<<dim3(32, 32), 256>>>(yt, yt, sqy, sqy, sp->Qyy,
                                                 &sp->segmin[1][0], &sp->rowmin[1][0]);
        cost_quant_kernel<<<dim3(32, 32), 256>>>(xt, yt, sqx, sqy, sp->QD,
                                                 &sp->segmin[2][0], &sp->rowmin[2][0]);
        transpose_q_kernel<<<dim3(128, 128), dim3(32, 8)>>>(sp->QD, sp->QDT,
                                                 &sp->segmin[3][0], &sp->rowmin[3][0]);

        quad_phase_kernel<<<NBLK, 512, QSMEM>>>(sp->Qxx, sp->Qyy, sp->QD, sp->QDT,
                                                segB, rowB, pots, fin);

        loss_reduce<<<1, 256>>>(fin, out, b == 0 ? 1 : 0);
    }
}